// round 6
// baseline (speedup 1.0000x reference)
#include <cuda_runtime.h>
#include <math.h>

#define MAX_NODES 50000
#define NPAD_CAP 51200
#define MAX_EDGES 800000
#define D 64
#define B 64
#define HL 128
#define SCAN_TILE 1024
#define POOL_CHUNK 1024
#define LAYER_BLOCKS 444
#define SMEM_FLOATS 16512   // wA4 4096 + wB4 4096 + rows 4096 + ts 4096 + 128

// ---------------- scratch (device globals; no allocation) ----------------
__device__ __align__(16) int g_counts[NPAD_CAP];
__device__ __align__(16) int g_offs[NPAD_CAP];
__device__ __align__(16) int g_cursor[NPAD_CAP];
__device__ unsigned long long g_tilestate[64];   // (flag<<32)|inclusive-or-aggregate
__device__ int g_elist[MAX_EDGES];
__device__ __align__(16) float g_h1[MAX_NODES * D];
__device__ __align__(16) float g_h2[MAX_NODES * D];
__device__ __align__(16) float g_sums[B * D];
__device__ float g_cntb[B];

// ---------------- packed f32x2 helpers ----------------
__device__ __forceinline__ void ffma2(unsigned long long& acc,
                                      unsigned long long a, unsigned long long b) {
    asm("fma.rn.f32x2 %0, %1, %2, %3;" : "=l"(acc) : "l"(a), "l"(b), "l"(acc));
}
__device__ __forceinline__ float f32x2_sum(unsigned long long v) {
    float lo = __uint_as_float((unsigned)(v & 0xffffffffull));
    float hi = __uint_as_float((unsigned)(v >> 32));
    return lo + hi;
}

// ---------------- count (+ zero pool accumulators in block 0) ----------------
__global__ void count_kernel(const int* __restrict__ ei, int n_edges,
                             int* __restrict__ counts,
                             float* __restrict__ sums, float* __restrict__ cnt) {
    if (blockIdx.x == 0) {
        for (int i = threadIdx.x; i < B * D; i += blockDim.x) sums[i] = 0.f;
        if (threadIdx.x < B) cnt[threadIdx.x] = 0.f;
    }
    int e = blockIdx.x * blockDim.x + threadIdx.x;
    if (e < n_edges) atomicAdd(&counts[__ldg(ei + n_edges + e)], 1);
}

// ---------------- single-pass scan with decoupled lookback ----------------
// grid <= 64 blocks, all resident -> lookback cannot deadlock.
__global__ void __launch_bounds__(256) scan_kernel(
        const int* __restrict__ counts, int* __restrict__ offs,
        int* __restrict__ cursor, unsigned long long* __restrict__ tilestate) {
    __shared__ int wsum[8];
    __shared__ int base_sh;
    int t = threadIdx.x;
    int lane = t & 31, warp = t >> 5;
    int b = blockIdx.x;
    int idx = b * SCAN_TILE + t * 4;
    int4 v = *(const int4*)(counts + idx);
    int s = v.x + v.y + v.z + v.w;
    int incl = s;
#pragma unroll
    for (int off = 1; off < 32; off <<= 1) {
        int u = __shfl_up_sync(0xffffffffu, incl, off);
        if (lane >= off) incl += u;
    }
    if (lane == 31) wsum[warp] = incl;
    __syncthreads();
    if (warp == 0) {
        int ws = (lane < 8) ? wsum[lane] : 0;
#pragma unroll
        for (int off = 1; off < 8; off <<= 1) {
            int u = __shfl_up_sync(0xffffffffu, ws, off);
            if (lane >= off) ws += u;
        }
        if (lane < 8) wsum[lane] = ws;
    }
    __syncthreads();
    int S = wsum[7];  // tile aggregate
    if (t == 0) {
        if (b == 0) {
            atomicExch(&tilestate[0], (2ull << 32) | (unsigned)S);
            base_sh = 0;
        } else {
            atomicExch(&tilestate[b], (1ull << 32) | (unsigned)S);
            int base = 0;
            int p = b - 1;
            while (true) {
                unsigned long long st = atomicAdd(&tilestate[p], 0ull);
                unsigned flag = (unsigned)(st >> 32);
                if (flag == 0) { __nanosleep(32); continue; }
                base += (int)(st & 0xffffffffull);
                if (flag == 2) break;
                p--;
            }
            atomicExch(&tilestate[b], (2ull << 32) | (unsigned)(base + S));
            base_sh = base;
        }
    }
    __syncthreads();
    int base = base_sh;
    int wbase = warp ? wsum[warp - 1] : 0;
    int ebase = base + wbase + incl - s;
    int4 e;
    e.x = ebase; e.y = ebase + v.x; e.z = e.y + v.y; e.w = e.z + v.z;
    *(int4*)(offs + idx) = e;
    *(int4*)(cursor + idx) = e;
}

// ---------------- fill edge list (4 edges/thread for ILP) ----------------
__global__ void fill_kernel(const int* __restrict__ ei, int n_edges,
                            int* __restrict__ cursor, int* __restrict__ elist) {
    int t = blockIdx.x * blockDim.x + threadIdx.x;
    int e0 = t * 4;
    if (e0 + 3 < n_edges) {
        int4 s = *(const int4*)(ei + e0);
        int4 d = *(const int4*)(ei + n_edges + e0);
        int p0 = atomicAdd(&cursor[d.x], 1);
        int p1 = atomicAdd(&cursor[d.y], 1);
        int p2 = atomicAdd(&cursor[d.z], 1);
        int p3 = atomicAdd(&cursor[d.w], 1);
        elist[p0] = s.x;
        elist[p1] = s.y;
        elist[p2] = s.z;
        elist[p3] = s.w;
    } else {
        for (int e = e0; e < n_edges; e++) {
            int s = __ldg(ei + e);
            int d = __ldg(ei + n_edges + e);
            int p = atomicAdd(&cursor[d], 1);
            elist[p] = s;
        }
    }
}

// ---------------- fused gather + GIN MLP (one layer per launch) ----------------
// out[i] = relu(relu((xin[i] + sum_{j in N(i)} feat[j]) @ wA.T + bA) @ wB.T + bB)
// Gather: lane L covers float4 column (L&15) of neighbor e+(L>>4); two
// neighbors per load instruction; halves combined with shfl_xor(16).
__global__ void __launch_bounds__(256, 3) layer_kernel(
        const float* __restrict__ feat, const float* __restrict__ xin,
        const float* __restrict__ wA, const float* __restrict__ bA,
        const float* __restrict__ wB, const float* __restrict__ bB,
        float* __restrict__ outbuf, int n) {
    extern __shared__ float smem[];
    float4* wA4 = (float4*)smem;
    float4* wB4 = (float4*)(smem + 4096);
    float* rowsbuf = smem + 8192;
    float* tsbuf = smem + 12288;
    float* bAs = smem + 16384;
    float* bBs = smem + 16448;

    int tid = threadIdx.x, warp = tid >> 5, lane = tid & 31;
    for (int idx = tid; idx < 1024; idx += 256) {
        int j0 = idx & 31, k = (idx >> 5) * 2;
        wA4[idx] = make_float4(wA[j0 * 64 + k], wA[j0 * 64 + k + 1],
                               wA[(j0 + 32) * 64 + k], wA[(j0 + 32) * 64 + k + 1]);
        wB4[idx] = make_float4(wB[j0 * 64 + k], wB[j0 * 64 + k + 1],
                               wB[(j0 + 32) * 64 + k], wB[(j0 + 32) * 64 + k + 1]);
    }
    if (tid < 64) { bAs[tid] = bA[tid]; bBs[tid] = bB[tid]; }
    __syncthreads();

    float* rows = rowsbuf + warp * 512;
    float* ts = tsbuf + warp * 512;
    unsigned rows_a = (unsigned)__cvta_generic_to_shared(rows);
    unsigned ts_a = (unsigned)__cvta_generic_to_shared(ts);
    unsigned wA_a = (unsigned)__cvta_generic_to_shared(wA4);
    unsigned wB_a = (unsigned)__cvta_generic_to_shared(wB4);

    float bAj0 = bAs[lane], bAj1 = bAs[lane + 32];
    float bBj0 = bBs[lane], bBj1 = bBs[lane + 32];

    int half = lane >> 4;     // 0/1: which neighbor of a pair
    int c4 = lane & 15;       // float4 column

    int ngroups = (n + 7) >> 3;
    for (int g = blockIdx.x * 8 + warp; g < ngroups; g += gridDim.x * 8) {
        int r0 = g * 8;
        // ---- gather 8 rows straight into smem ----
        for (int i = 0; i < 8; i++) {
            int node = r0 + i;
            float4 a0 = make_float4(0.f, 0.f, 0.f, 0.f);
            if (node < n) {
                int start = __ldg(g_offs + node);
                int deg = __ldg(g_counts + node);
                if (half == 0)
                    a0 = __ldg((const float4*)(xin + (size_t)node * 64) + c4);
                float4 a1 = make_float4(0.f, 0.f, 0.f, 0.f);
                float4 a2 = make_float4(0.f, 0.f, 0.f, 0.f);
                float4 a3 = make_float4(0.f, 0.f, 0.f, 0.f);
                int e = 0;
                for (; e + 7 < deg; e += 8) {
                    int s0 = __ldg(g_elist + start + e);
                    int s1 = __ldg(g_elist + start + e + 1);
                    int s2 = __ldg(g_elist + start + e + 2);
                    int s3 = __ldg(g_elist + start + e + 3);
                    int s4 = __ldg(g_elist + start + e + 4);
                    int s5 = __ldg(g_elist + start + e + 5);
                    int s6 = __ldg(g_elist + start + e + 6);
                    int s7 = __ldg(g_elist + start + e + 7);
                    int i0 = half ? s1 : s0;
                    int i1 = half ? s3 : s2;
                    int i2 = half ? s5 : s4;
                    int i3 = half ? s7 : s6;
                    float4 v0 = __ldg((const float4*)(feat + (size_t)i0 * 64) + c4);
                    float4 v1 = __ldg((const float4*)(feat + (size_t)i1 * 64) + c4);
                    float4 v2 = __ldg((const float4*)(feat + (size_t)i2 * 64) + c4);
                    float4 v3 = __ldg((const float4*)(feat + (size_t)i3 * 64) + c4);
                    a0.x += v0.x; a0.y += v0.y; a0.z += v0.z; a0.w += v0.w;
                    a1.x += v1.x; a1.y += v1.y; a1.z += v1.z; a1.w += v1.w;
                    a2.x += v2.x; a2.y += v2.y; a2.z += v2.z; a2.w += v2.w;
                    a3.x += v3.x; a3.y += v3.y; a3.z += v3.z; a3.w += v3.w;
                }
                for (; e < deg; e += 2) {
                    int sA = __ldg(g_elist + start + e);
                    bool have2 = (e + 1 < deg);
                    int sB = have2 ? __ldg(g_elist + start + e + 1) : sA;
                    int ii = half ? sB : sA;
                    if (!half || have2) {
                        float4 v = __ldg((const float4*)(feat + (size_t)ii * 64) + c4);
                        a0.x += v.x; a0.y += v.y; a0.z += v.z; a0.w += v.w;
                    }
                }
                a0.x += a1.x + a2.x + a3.x;
                a0.y += a1.y + a2.y + a3.y;
                a0.z += a1.z + a2.z + a3.z;
                a0.w += a1.w + a2.w + a3.w;
                // combine the two neighbor-halves
                a0.x += __shfl_xor_sync(0xffffffffu, a0.x, 16);
                a0.y += __shfl_xor_sync(0xffffffffu, a0.y, 16);
                a0.z += __shfl_xor_sync(0xffffffffu, a0.z, 16);
                a0.w += __shfl_xor_sync(0xffffffffu, a0.w, 16);
            }
            if (half == 0)
                ((float4*)(rows + i * 64))[c4] = a0;
        }
        __syncwarp();

        // ---- phase 1: t = relu(rows @ wA.T + bA) ----
        unsigned long long acc[8][2];
#pragma unroll
        for (int i = 0; i < 8; i++) { acc[i][0] = 0ull; acc[i][1] = 0ull; }
#pragma unroll 4
        for (int k2 = 0; k2 < 32; k2++) {
            unsigned long long w0, w1;
            asm volatile("ld.shared.v2.u64 {%0,%1}, [%2];"
                         : "=l"(w0), "=l"(w1) : "r"(wA_a + (k2 * 32 + lane) * 16));
#pragma unroll
            for (int i = 0; i < 8; i++) {
                unsigned long long h2;
                asm volatile("ld.shared.b64 %0, [%1];"
                             : "=l"(h2) : "r"(rows_a + i * 256 + k2 * 8));
                ffma2(acc[i][0], h2, w0);
                ffma2(acc[i][1], h2, w1);
            }
        }
#pragma unroll
        for (int i = 0; i < 8; i++) {
            ts[i * 64 + lane] = fmaxf(f32x2_sum(acc[i][0]) + bAj0, 0.f);
            ts[i * 64 + lane + 32] = fmaxf(f32x2_sum(acc[i][1]) + bAj1, 0.f);
        }
        __syncwarp();

        // ---- phase 2: out = relu(t @ wB.T + bB) ----
#pragma unroll
        for (int i = 0; i < 8; i++) { acc[i][0] = 0ull; acc[i][1] = 0ull; }
#pragma unroll 4
        for (int k2 = 0; k2 < 32; k2++) {
            unsigned long long w0, w1;
            asm volatile("ld.shared.v2.u64 {%0,%1}, [%2];"
                         : "=l"(w0), "=l"(w1) : "r"(wB_a + (k2 * 32 + lane) * 16));
#pragma unroll
            for (int i = 0; i < 8; i++) {
                unsigned long long h2;
                asm volatile("ld.shared.b64 %0, [%1];"
                             : "=l"(h2) : "r"(ts_a + i * 256 + k2 * 8));
                ffma2(acc[i][0], h2, w0);
                ffma2(acc[i][1], h2, w1);
            }
        }
        int nr = min(8, n - r0);
        for (int i = 0; i < nr; i++) {
            outbuf[(size_t)(r0 + i) * 64 + lane] = fmaxf(f32x2_sum(acc[i][0]) + bBj0, 0.f);
            outbuf[(size_t)(r0 + i) * 64 + lane + 32] = fmaxf(f32x2_sum(acc[i][1]) + bBj1, 0.f);
        }
        __syncwarp();
    }
}

// ---------------- mean-pool over sorted batch ----------------
__global__ void pool_kernel(const float* __restrict__ h,
                            const int* __restrict__ batch, int n,
                            float* __restrict__ sums, float* __restrict__ cnt) {
    int d = threadIdx.x & 63;
    int sub = threadIdx.x >> 6;
    int start = blockIdx.x * POOL_CHUNK + sub;
    int end = min(blockIdx.x * POOL_CHUNK + POOL_CHUNK, n);
    float acc = 0.f, c = 0.f;
    int cur = -1;
    for (int r = start; r < end; r += 4) {
        int b = __ldg(batch + r);
        if (b != cur) {
            if (cur >= 0) {
                atomicAdd(&sums[cur * 64 + d], acc);
                if (d == 0) atomicAdd(&cnt[cur], c);
            }
            cur = b; acc = 0.f; c = 0.f;
        }
        acc += h[(size_t)r * 64 + d];
        c += 1.f;
    }
    if (cur >= 0) {
        atomicAdd(&sums[cur * 64 + d], acc);
        if (d == 0) atomicAdd(&cnt[cur], c);
    }
}

// ---------------- fused gates + LSTM cell + FC + softmax ----------------
__global__ void __launch_bounds__(256) tail_kernel(
        const float* __restrict__ sums, const float* __restrict__ cnt,
        const float* __restrict__ h0, const float* __restrict__ c0,
        const float* __restrict__ w_ih, const float* __restrict__ w_hh,
        const float* __restrict__ b_ih, const float* __restrict__ b_hh,
        const float* __restrict__ fc_w, const float* __restrict__ fc_b,
        float* __restrict__ out) {
    __shared__ float ps[64];
    __shared__ float h0s[128];
    __shared__ float gsm[512];
    __shared__ float h1s[128];
    int b = blockIdx.x;
    int tid = threadIdx.x;
    if (tid < 64) ps[tid] = sums[b * 64 + tid] / fmaxf(cnt[b], 1.f);
    if (tid >= 64 && tid < 192) h0s[tid - 64] = h0[b * 128 + (tid - 64)];
    __syncthreads();
#pragma unroll
    for (int jj = 0; jj < 2; jj++) {
        int j = tid + jj * 256;
        float acc = b_ih[j] + b_hh[j];
        const float4* wi = (const float4*)(w_ih + (size_t)j * 64);
#pragma unroll
        for (int k4 = 0; k4 < 16; k4++) {
            float4 w = __ldg(wi + k4);
            acc += w.x * ps[k4 * 4] + w.y * ps[k4 * 4 + 1]
                 + w.z * ps[k4 * 4 + 2] + w.w * ps[k4 * 4 + 3];
        }
        const float4* wh = (const float4*)(w_hh + (size_t)j * 128);
#pragma unroll
        for (int k4 = 0; k4 < 32; k4++) {
            float4 w = __ldg(wh + k4);
            acc += w.x * h0s[k4 * 4] + w.y * h0s[k4 * 4 + 1]
                 + w.z * h0s[k4 * 4 + 2] + w.w * h0s[k4 * 4 + 3];
        }
        gsm[j] = acc;
    }
    __syncthreads();
    if (tid < 128) {
        float gi = gsm[tid], gf = gsm[128 + tid];
        float gg = gsm[256 + tid], go = gsm[384 + tid];
        float si = 1.f / (1.f + expf(-gi));
        float sf = 1.f / (1.f + expf(-gf));
        float so = 1.f / (1.f + expf(-go));
        float c1 = sf * c0[b * 128 + tid] + si * tanhf(gg);
        float h1v = so * tanhf(c1);
        out[B * 32 + b * 128 + tid] = h1v;
        out[B * 32 + B * 128 + b * 128 + tid] = c1;
        h1s[tid] = h1v;
    }
    __syncthreads();
    if (tid < 32) {
        float acc = fc_b[tid];
        const float4* fw = (const float4*)(fc_w + (size_t)tid * 128);
#pragma unroll
        for (int k4 = 0; k4 < 32; k4++) {
            float4 w = __ldg(fw + k4);
            acc += w.x * h1s[k4 * 4] + w.y * h1s[k4 * 4 + 1]
                 + w.z * h1s[k4 * 4 + 2] + w.w * h1s[k4 * 4 + 3];
        }
        float m = acc;
        for (int off = 16; off; off >>= 1)
            m = fmaxf(m, __shfl_xor_sync(0xffffffffu, m, off));
        float e = expf(acc - m);
        float s = e;
        for (int off = 16; off; off >>= 1)
            s += __shfl_xor_sync(0xffffffffu, s, off);
        out[b * 32 + tid] = e / s;
    }
}

// ---------------- launch ----------------
extern "C" void kernel_launch(void* const* d_in, const int* in_sizes, int n_in,
                              void* d_out, int out_size) {
    const float* x     = (const float*)d_in[0];
    const int*   ei    = (const int*)d_in[1];
    const int*   batch = (const int*)d_in[2];
    const float* w1    = (const float*)d_in[3];
    const float* b1    = (const float*)d_in[4];
    const float* w2    = (const float*)d_in[5];
    const float* b2    = (const float*)d_in[6];
    const float* w3    = (const float*)d_in[7];
    const float* b3    = (const float*)d_in[8];
    const float* w4    = (const float*)d_in[9];
    const float* b4    = (const float*)d_in[10];
    const float* w_ih  = (const float*)d_in[11];
    const float* w_hh  = (const float*)d_in[12];
    const float* b_ih  = (const float*)d_in[13];
    const float* b_hh  = (const float*)d_in[14];
    const float* fc_w  = (const float*)d_in[15];
    const float* fc_b  = (const float*)d_in[16];
    const float* h0    = (const float*)d_in[17];
    const float* c0    = (const float*)d_in[18];
    float* out = (float*)d_out;

    int n_nodes = in_sizes[0] / 64;
    int n_edges = in_sizes[1] / 2;
    int npad = (n_nodes + SCAN_TILE - 1) & ~(SCAN_TILE - 1);
    int nsb = npad / SCAN_TILE;

    int* counts;    cudaGetSymbolAddress((void**)&counts, g_counts);
    int* offs;      cudaGetSymbolAddress((void**)&offs, g_offs);
    int* cursor;    cudaGetSymbolAddress((void**)&cursor, g_cursor);
    unsigned long long* tilestate;
    cudaGetSymbolAddress((void**)&tilestate, g_tilestate);
    int* elist;     cudaGetSymbolAddress((void**)&elist, g_elist);
    float* h1;      cudaGetSymbolAddress((void**)&h1, g_h1);
    float* h2;      cudaGetSymbolAddress((void**)&h2, g_h2);
    float* sums;    cudaGetSymbolAddress((void**)&sums, g_sums);
    float* cnt;     cudaGetSymbolAddress((void**)&cnt, g_cntb);

    cudaFuncSetAttribute(layer_kernel, cudaFuncAttributeMaxDynamicSharedMemorySize,
                         SMEM_FLOATS * 4);

    int eb = (n_edges + 255) / 256;
    int fb = ((n_edges + 3) / 4 + 255) / 256;
    int pool_blocks = (n_nodes + POOL_CHUNK - 1) / POOL_CHUNK;

    // ---- CSR build ----
    cudaMemsetAsync(counts, 0, npad * sizeof(int));
    cudaMemsetAsync(tilestate, 0, 64 * sizeof(unsigned long long));
    count_kernel<<<eb, 256>>>(ei, n_edges, counts, sums, cnt);          // launch 1
    scan_kernel<<<nsb, 256>>>(counts, offs, cursor, tilestate);          // launch 2
    fill_kernel<<<fb, 256>>>(ei, n_edges, cursor, elist);                // launch 3

    // ---- layers (gather fused into MLP); layer1 is the profiled 4th launch ----
    layer_kernel<<<LAYER_BLOCKS, 256, SMEM_FLOATS * 4>>>(x, x, w1, b1, w2, b2, h1, n_nodes);
    layer_kernel<<<LAYER_BLOCKS, 256, SMEM_FLOATS * 4>>>(h1, h1, w3, b3, w4, b4, h2, n_nodes);

    // ---- pooling ----
    pool_kernel<<<pool_blocks, 256>>>(h2, batch, n_nodes, sums, cnt);

    // ---- LSTM + FC + softmax ----
    tail_kernel<<<B, 256>>>(sums, cnt, h0, c0, w_ih, w_hh, b_ih, b_hh, fc_w, fc_b, out);
}